// round 7
// baseline (speedup 1.0000x reference)
#include <cuda_runtime.h>
#include <cuda_bf16.h>
#include <cstdint>

// out = x @ (w1@w2@w3@w4) per expert; every GEMM = bf16 hi/lo split (3 HMMA terms),
// computed as D[M,N] = A[M,K] * Bt[N,K]^T via mma.sync.m16n8k16 (sm_80+ PTX only —
// tcgen05 is rejected because the harness compiles through compute_103 virtual arch).
// R7: warp tile 64x32 (was 32x64) -> 12 ldmatrix per k16 (was 16); single sync/chunk;
//     launch order puts GEMM S2 at index 5 for the ncu capture.

#define NE 8
#define NT 4096
#define NH 1024
#define NI 512

// ---------------- scratch ----------------
__device__ __align__(128) __nv_bfloat16 g_xh[NE*NT*NH],  g_xl[NE*NT*NH];
__device__ __align__(128) __nv_bfloat16 g_w1h[NE*NH*NI], g_w1l[NE*NH*NI];
__device__ __align__(128) __nv_bfloat16 g_w2h[NE*NH*NI], g_w2l[NE*NH*NI];   // w2^T
__device__ __align__(128) __nv_bfloat16 g_w3h[NE*NH*NI], g_w3l[NE*NH*NI];
__device__ __align__(128) __nv_bfloat16 g_w4h[NE*NH*NI], g_w4l[NE*NH*NI];   // w4^T
__device__ __align__(128) __nv_bfloat16 g_W12h[NE*NH*NH], g_W12l[NE*NH*NH];
__device__ __align__(128) __nv_bfloat16 g_W34h[NE*NH*NH], g_W34l[NE*NH*NH]; // W34^T
__device__ __align__(128) __nv_bfloat16 g_Wth[NE*NH*NH],  g_Wtl[NE*NH*NH];  // W^T

__device__ __forceinline__ void split1(float v, __nv_bfloat16& h, __nv_bfloat16& l) {
    h = __float2bfloat16(v);
    l = __float2bfloat16(v - __bfloat162float(h));
}

// ---------------- conversion kernels ----------------
__global__ __launch_bounds__(256)
void split_rm(const float4* __restrict__ in, uint2* __restrict__ hi,
              uint2* __restrict__ lo, int n4) {
    int i = blockIdx.x * 256 + threadIdx.x;
    if (i >= n4) return;
    float4 v = in[i];
    __nv_bfloat16 h[4], l[4];
    split1(v.x, h[0], l[0]); split1(v.y, h[1], l[1]);
    split1(v.z, h[2], l[2]); split1(v.w, h[3], l[3]);
    hi[i] = *(uint2*)h;
    lo[i] = *(uint2*)l;
}

// in: [E, R, C] fp32 -> out: [E, C, R] bf16 hi/lo
__global__ __launch_bounds__(256)
void split_tr(const float* __restrict__ in, __nv_bfloat16* __restrict__ hi,
              __nv_bfloat16* __restrict__ lo, int R, int C) {
    __shared__ float t[32][33];
    const int e = blockIdx.z;
    const float* ine = in + (size_t)e * R * C;
    __nv_bfloat16* he = hi + (size_t)e * R * C;
    __nv_bfloat16* le = lo + (size_t)e * R * C;
    const int r0 = blockIdx.y * 32, c0 = blockIdx.x * 32;
    const int tx = threadIdx.x & 31, ty = threadIdx.x >> 5;
    #pragma unroll
    for (int i = 0; i < 32; i += 8)
        t[ty + i][tx] = ine[(size_t)(r0 + ty + i) * C + c0 + tx];
    __syncthreads();
    #pragma unroll
    for (int i = 0; i < 32; i += 8) {
        __nv_bfloat16 h, l;
        split1(t[tx][ty + i], h, l);
        he[(size_t)(c0 + ty + i) * R + r0 + tx] = h;
        le[(size_t)(c0 + ty + i) * R + r0 + tx] = l;
    }
}

// ---------------- HMMA bf16x3 GEMM ----------------
// CTA 128x128, BK=32. 8 warps in 2(M) x 4(N); warp tile 64x32.
// SMEM rows padded to 80B -> ldmatrix conflict-free.
#define BM 128
#define BN 128
#define BKC 32
#define ROWB 80u
#define TILEB (128u * ROWB)      // 10240 B per 128x32 tile
#define BUFB (4u * TILEB)        // Ah | Al | Bh | Bl
#define SMEMB (2u * BUFB)        // 81920 B double-buffered

__device__ __forceinline__ void cp16(uint32_t s, const void* g) {
    asm volatile("cp.async.cg.shared.global [%0], [%1], 16;" :: "r"(s), "l"(g));
}
__device__ __forceinline__ void ldm4(uint32_t* r, uint32_t addr) {
    asm volatile("ldmatrix.sync.aligned.m8n8.x4.shared.b16 {%0,%1,%2,%3}, [%4];"
                 : "=r"(r[0]), "=r"(r[1]), "=r"(r[2]), "=r"(r[3]) : "r"(addr));
}
__device__ __forceinline__ void mma16816(float* c, const uint32_t* a, uint32_t b0, uint32_t b1) {
    asm volatile("mma.sync.aligned.m16n8k16.row.col.f32.bf16.bf16.f32 "
                 "{%0,%1,%2,%3}, {%4,%5,%6,%7}, {%8,%9}, {%0,%1,%2,%3};"
                 : "+f"(c[0]), "+f"(c[1]), "+f"(c[2]), "+f"(c[3])
                 : "r"(a[0]), "r"(a[1]), "r"(a[2]), "r"(a[3]), "r"(b0), "r"(b1));
}

template<bool SPLIT_OUT>
__global__ __launch_bounds__(256, 2)
void gemm_hmma_x3(const __nv_bfloat16* __restrict__ Ah, const __nv_bfloat16* __restrict__ Al,
                  const __nv_bfloat16* __restrict__ Bh, const __nv_bfloat16* __restrict__ Bl,
                  float* __restrict__ Cf,
                  __nv_bfloat16* __restrict__ Ch, __nv_bfloat16* __restrict__ Cl,
                  int M, int N, int K)
{
    extern __shared__ __align__(128) char smem[];
    const uint32_t sb = (uint32_t)__cvta_generic_to_shared(smem);

    const int tid = threadIdx.x;
    const int lane = tid & 31;
    const int wid = tid >> 5;
    const int wm = (wid >> 2) * 64;  // warp M offset: 2 groups
    const int wn = (wid & 3) * 32;   // warp N offset: 4 groups
    const int g = lane >> 3, r8 = lane & 7;

    const int e = blockIdx.z;
    const size_t MK = (size_t)M * K, NK = (size_t)N * K, MN = (size_t)M * N;
    const __nv_bfloat16 *Ahe = Ah + e * MK, *Ale = Al + e * MK;
    const __nv_bfloat16 *Bhe = Bh + e * NK, *Ble = Bl + e * NK;
    const int bm = blockIdx.y * BM, bn = blockIdx.x * BN;

    float acc[4][4][4];
    #pragma unroll
    for (int i = 0; i < 4; i++)
        #pragma unroll
        for (int j = 0; j < 4; j++)
            #pragma unroll
            for (int q = 0; q < 4; q++) acc[i][j][q] = 0.0f;

    const int NC = K / BKC;

    // per-thread copy coords: 2 chunks of 16B per 128x32 tile
    const int cr0 = tid >> 2,          cc0 = tid & 3;
    const int cr1 = (tid + 256) >> 2,  cc1 = (tid + 256) & 3;

    auto load_chunk = [&](int c, int buf) {
        const int k0 = c * BKC;
        const uint32_t b = sb + (uint32_t)buf * BUFB;
        cp16(b + cr0 * ROWB + cc0 * 16, Ahe + (size_t)(bm + cr0) * K + k0 + cc0 * 8);
        cp16(b + cr1 * ROWB + cc1 * 16, Ahe + (size_t)(bm + cr1) * K + k0 + cc1 * 8);
        cp16(b + TILEB + cr0 * ROWB + cc0 * 16, Ale + (size_t)(bm + cr0) * K + k0 + cc0 * 8);
        cp16(b + TILEB + cr1 * ROWB + cc1 * 16, Ale + (size_t)(bm + cr1) * K + k0 + cc1 * 8);
        cp16(b + 2 * TILEB + cr0 * ROWB + cc0 * 16, Bhe + (size_t)(bn + cr0) * K + k0 + cc0 * 8);
        cp16(b + 2 * TILEB + cr1 * ROWB + cc1 * 16, Bhe + (size_t)(bn + cr1) * K + k0 + cc1 * 8);
        cp16(b + 3 * TILEB + cr0 * ROWB + cc0 * 16, Ble + (size_t)(bn + cr0) * K + k0 + cc0 * 8);
        cp16(b + 3 * TILEB + cr1 * ROWB + cc1 * 16, Ble + (size_t)(bn + cr1) * K + k0 + cc1 * 8);
        asm volatile("cp.async.commit_group;" ::: "memory");
    };

    load_chunk(0, 0);

    for (int c = 0; c < NC; c++) {
        const int cur = c & 1;
        // chunk c's group is the only one outstanding
        asm volatile("cp.async.wait_group 0;" ::: "memory");
        __syncthreads();   // data visible + everyone done reading buffer cur^1

        if (c + 1 < NC) load_chunk(c + 1, cur ^ 1);

        const uint32_t As  = sb + (uint32_t)cur * BUFB;
        const uint32_t Als = As + TILEB;
        const uint32_t Bs  = As + 2 * TILEB;
        const uint32_t Bls = As + 3 * TILEB;

        #pragma unroll
        for (int ks = 0; ks < 2; ks++) {
            uint32_t ah[4][4], bbh[2][4], bbl[2][4];
            // A hi fragments: ti covers rows wm+ti*16 .. +15
            #pragma unroll
            for (int ti = 0; ti < 4; ti++) {
                uint32_t off = (uint32_t)(wm + ti * 16 + (g & 1) * 8 + r8) * ROWB
                             + ks * 32 + (g >> 1) * 16;
                ldm4(ah[ti], As + off);
            }
            // B hi+lo fragments: pair p covers n-octets 2p, 2p+1
            #pragma unroll
            for (int p = 0; p < 2; p++) {
                uint32_t off = (uint32_t)(wn + p * 16 + (g >> 1) * 8 + r8) * ROWB
                             + ks * 32 + (g & 1) * 16;
                ldm4(bbh[p], Bs + off);
                ldm4(bbl[p], Bls + off);
            }
            // hi*hi and hi*lo
            #pragma unroll
            for (int ti = 0; ti < 4; ti++)
                #pragma unroll
                for (int tj = 0; tj < 4; tj++) {
                    mma16816(acc[ti][tj], ah[ti],
                             bbh[tj >> 1][(tj & 1) * 2], bbh[tj >> 1][(tj & 1) * 2 + 1]);
                    mma16816(acc[ti][tj], ah[ti],
                             bbl[tj >> 1][(tj & 1) * 2], bbl[tj >> 1][(tj & 1) * 2 + 1]);
                }
            // A lo overwrites the ah registers (keeps pressure under the 128-reg cap)
            #pragma unroll
            for (int ti = 0; ti < 4; ti++) {
                uint32_t off = (uint32_t)(wm + ti * 16 + (g & 1) * 8 + r8) * ROWB
                             + ks * 32 + (g >> 1) * 16;
                ldm4(ah[ti], Als + off);
            }
            // lo*hi
            #pragma unroll
            for (int ti = 0; ti < 4; ti++)
                #pragma unroll
                for (int tj = 0; tj < 4; tj++)
                    mma16816(acc[ti][tj], ah[ti],
                             bbh[tj >> 1][(tj & 1) * 2], bbh[tj >> 1][(tj & 1) * 2 + 1]);
        }
        __syncthreads();   // done reading cur before iteration c+2 overwrites it
    }

    // epilogue
    #pragma unroll
    for (int ti = 0; ti < 4; ti++)
        #pragma unroll
        for (int tj = 0; tj < 4; tj++) {
            const int row = bm + wm + ti * 16 + (lane >> 2);
            const int col = bn + wn + tj * 8 + (lane & 3) * 2;
            if (SPLIT_OUT) {
                __nv_bfloat16 h0, l0, h1, l1;
                split1(acc[ti][tj][0], h0, l0); split1(acc[ti][tj][1], h1, l1);
                __nv_bfloat16 hp[2] = {h0, h1}, lp[2] = {l0, l1};
                *(uint32_t*)(Ch + e * MN + (size_t)row * N + col) = *(uint32_t*)hp;
                *(uint32_t*)(Cl + e * MN + (size_t)row * N + col) = *(uint32_t*)lp;
                split1(acc[ti][tj][2], h0, l0); split1(acc[ti][tj][3], h1, l1);
                __nv_bfloat16 hq[2] = {h0, h1}, lq[2] = {l0, l1};
                *(uint32_t*)(Ch + e * MN + (size_t)(row + 8) * N + col) = *(uint32_t*)hq;
                *(uint32_t*)(Cl + e * MN + (size_t)(row + 8) * N + col) = *(uint32_t*)lq;
            } else {
                float* cp0 = Cf + e * MN + (size_t)row * N + col;
                float* cp1 = Cf + e * MN + (size_t)(row + 8) * N + col;
                *(float2*)cp0 = make_float2(acc[ti][tj][0], acc[ti][tj][1]);
                *(float2*)cp1 = make_float2(acc[ti][tj][2], acc[ti][tj][3]);
            }
        }
}

// ---------------- launcher ----------------
extern "C" void kernel_launch(void* const* d_in, const int* in_sizes, int n_in,
                              void* d_out, int out_size)
{
    (void)in_sizes; (void)n_in; (void)out_size;
    const float* x  = (const float*)d_in[0];
    const float* w1 = (const float*)d_in[1];
    const float* w2 = (const float*)d_in[2];
    const float* w3 = (const float*)d_in[3];
    const float* w4 = (const float*)d_in[4];
    float* out = (float*)d_out;

    __nv_bfloat16 *xh,*xl,*w1h,*w1l,*w2h,*w2l,*w3h,*w3l,*w4h,*w4l;
    __nv_bfloat16 *W12h,*W12l,*W34h,*W34l,*Wth,*Wtl;
    cudaGetSymbolAddress((void**)&xh,  g_xh);  cudaGetSymbolAddress((void**)&xl,  g_xl);
    cudaGetSymbolAddress((void**)&w1h, g_w1h); cudaGetSymbolAddress((void**)&w1l, g_w1l);
    cudaGetSymbolAddress((void**)&w2h, g_w2h); cudaGetSymbolAddress((void**)&w2l, g_w2l);
    cudaGetSymbolAddress((void**)&w3h, g_w3h); cudaGetSymbolAddress((void**)&w3l, g_w3l);
    cudaGetSymbolAddress((void**)&w4h, g_w4h); cudaGetSymbolAddress((void**)&w4l, g_w4l);
    cudaGetSymbolAddress((void**)&W12h, g_W12h); cudaGetSymbolAddress((void**)&W12l, g_W12l);
    cudaGetSymbolAddress((void**)&W34h, g_W34h); cudaGetSymbolAddress((void**)&W34l, g_W34l);
    cudaGetSymbolAddress((void**)&Wth,  g_Wth);  cudaGetSymbolAddress((void**)&Wtl,  g_Wtl);

    cudaFuncSetAttribute(gemm_hmma_x3<true>,  cudaFuncAttributeMaxDynamicSharedMemorySize, SMEMB);
    cudaFuncSetAttribute(gemm_hmma_x3<false>, cudaFuncAttributeMaxDynamicSharedMemorySize, SMEMB);

    // weight conversions first (launch idx 0-3) so idx 5 = GEMM S2 for the ncu capture
    {
        int n4 = NE * NH * NI / 4;
        split_rm<<<n4 / 256, 256>>>((const float4*)w1, (uint2*)w1h, (uint2*)w1l, n4);
        split_rm<<<n4 / 256, 256>>>((const float4*)w3, (uint2*)w3h, (uint2*)w3l, n4);
    }
    split_tr<<<dim3(NH / 32, NI / 32, NE), 256>>>(w2, w2h, w2l, NI, NH);
    split_tr<<<dim3(NH / 32, NI / 32, NE), 256>>>(w4, w4h, w4l, NI, NH);

    // S1 (idx 4): W12 = w1 @ w2      (A=w1,  Bt=w2^T)  M=N=1024, K=512
    gemm_hmma_x3<true><<<dim3(NH / BN, NH / BM, NE), 256, SMEMB>>>(
        w1h, w1l, w2h, w2l, nullptr, W12h, W12l, NH, NH, NI);
    // S2 (idx 5, ncu capture target): W34^T = w4^T @ w3^T
    gemm_hmma_x3<true><<<dim3(NH / BN, NH / BM, NE), 256, SMEMB>>>(
        w4h, w4l, w3h, w3l, nullptr, W34h, W34l, NH, NH, NI);
    // S3 (idx 6): W^T = W34^T @ W12^T  M=N=K=1024
    gemm_hmma_x3<true><<<dim3(NH / BN, NH / BM, NE), 256, SMEMB>>>(
        W34h, W34l, W12h, W12l, nullptr, Wth, Wtl, NH, NH, NH);
    // x conversion (idx 7)
    {
        int n4 = NE * NT * NH / 4;
        split_rm<<<n4 / 256, 256>>>((const float4*)x, (uint2*)xh, (uint2*)xl, n4);
    }
    // S4 (idx 8): out = x @ W   M=4096(per e), N=K=1024
    gemm_hmma_x3<false><<<dim3(NH / BN, NT / BM, NE), 256, SMEMB>>>(
        xh, xl, Wth, Wtl, out, nullptr, nullptr, NT, NH, NH);
}

// round 8
// speedup vs baseline: 1.4291x; 1.4291x over previous
#include <cuda_runtime.h>
#include <cuda_fp16.h>
#include <cstdint>

// out = x @ (w1@w2@w3@w4) per expert.
// Every GEMM = fp16 2-term: D = Ah @ (Bh + Bl)^T, A rounded to fp16 (hi only),
// B split into fp16 hi+lo. Error per stage ~1e-4 (norm), 4 stages ~3e-4 < 1e-3.
// mma.sync.m16n8k16.f32.f16.f16.f32 (sm_80+ PTX; tcgen05 rejected by compute_103).
// R8: 2 MMAs/tile (was 3, -33% HMMA), no A-lo tile, 3-stage cp.async ring with
//     single __syncthreads per chunk.

#define NE 8
#define NT 4096
#define NH 1024
#define NI 512

// ---------------- scratch ----------------
__device__ __align__(128) __half g_xh[NE*NT*NH];
__device__ __align__(128) __half g_w1h[NE*NH*NI];
__device__ __align__(128) __half g_w2h[NE*NH*NI], g_w2l[NE*NH*NI];   // w2^T hi/lo
__device__ __align__(128) __half g_w3h[NE*NH*NI], g_w3l[NE*NH*NI];
__device__ __align__(128) __half g_w4h[NE*NH*NI];                    // w4^T hi
__device__ __align__(128) __half g_W12h[NE*NH*NH], g_W12l[NE*NH*NH];
__device__ __align__(128) __half g_W34h[NE*NH*NH];                   // W34^T hi
__device__ __align__(128) __half g_Wth[NE*NH*NH],  g_Wtl[NE*NH*NH];  // W^T hi/lo

__device__ __forceinline__ void split1(float v, __half& h, __half& l) {
    h = __float2half(v);
    l = __float2half(v - __half2float(h));
}

// ---------------- conversion kernels ----------------
__global__ __launch_bounds__(256)
void half_rm(const float4* __restrict__ in, uint2* __restrict__ hi, int n4) {
    int i = blockIdx.x * 256 + threadIdx.x;
    if (i >= n4) return;
    float4 v = in[i];
    __half h[4] = {__float2half(v.x), __float2half(v.y),
                   __float2half(v.z), __float2half(v.w)};
    hi[i] = *(uint2*)h;
}

__global__ __launch_bounds__(256)
void split_rm(const float4* __restrict__ in, uint2* __restrict__ hi,
              uint2* __restrict__ lo, int n4) {
    int i = blockIdx.x * 256 + threadIdx.x;
    if (i >= n4) return;
    float4 v = in[i];
    __half h[4], l[4];
    split1(v.x, h[0], l[0]); split1(v.y, h[1], l[1]);
    split1(v.z, h[2], l[2]); split1(v.w, h[3], l[3]);
    hi[i] = *(uint2*)h;
    lo[i] = *(uint2*)l;
}

// in: [E, R, C] fp32 -> out hi: [E, C, R]
__global__ __launch_bounds__(256)
void half_tr(const float* __restrict__ in, __half* __restrict__ hi, int R, int C) {
    __shared__ float t[32][33];
    const int e = blockIdx.z;
    const float* ine = in + (size_t)e * R * C;
    __half* he = hi + (size_t)e * R * C;
    const int r0 = blockIdx.y * 32, c0 = blockIdx.x * 32;
    const int tx = threadIdx.x & 31, ty = threadIdx.x >> 5;
    #pragma unroll
    for (int i = 0; i < 32; i += 8)
        t[ty + i][tx] = ine[(size_t)(r0 + ty + i) * C + c0 + tx];
    __syncthreads();
    #pragma unroll
    for (int i = 0; i < 32; i += 8)
        he[(size_t)(c0 + ty + i) * R + r0 + tx] = __float2half(t[tx][ty + i]);
}

// in: [E, R, C] fp32 -> out hi/lo: [E, C, R]
__global__ __launch_bounds__(256)
void split_tr(const float* __restrict__ in, __half* __restrict__ hi,
              __half* __restrict__ lo, int R, int C) {
    __shared__ float t[32][33];
    const int e = blockIdx.z;
    const float* ine = in + (size_t)e * R * C;
    __half* he = hi + (size_t)e * R * C;
    __half* le = lo + (size_t)e * R * C;
    const int r0 = blockIdx.y * 32, c0 = blockIdx.x * 32;
    const int tx = threadIdx.x & 31, ty = threadIdx.x >> 5;
    #pragma unroll
    for (int i = 0; i < 32; i += 8)
        t[ty + i][tx] = ine[(size_t)(r0 + ty + i) * C + c0 + tx];
    __syncthreads();
    #pragma unroll
    for (int i = 0; i < 32; i += 8) {
        __half h, l;
        split1(t[tx][ty + i], h, l);
        he[(size_t)(c0 + ty + i) * R + r0 + tx] = h;
        le[(size_t)(c0 + ty + i) * R + r0 + tx] = l;
    }
}

// ---------------- HMMA fp16 2-term GEMM ----------------
// CTA 128x128, BK=32. 8 warps 2(M) x 4(N); warp tile 64x32.
// SMEM rows padded to 80B. 3-stage cp.async ring, 1 sync per chunk.
#define BM 128
#define BN 128
#define BKC 32
#define ROWB 80u
#define TILEB (128u * ROWB)       // 10240 B per 128x32 tile
#define BUFB (3u * TILEB)         // Ah | Bh | Bl = 30720 B
#define NSTAGE 3
#define SMEMB (3u * BUFB)         // 92160 B

__device__ __forceinline__ void cp16(uint32_t s, const void* g) {
    asm volatile("cp.async.cg.shared.global [%0], [%1], 16;" :: "r"(s), "l"(g));
}
__device__ __forceinline__ void ldm4(uint32_t* r, uint32_t addr) {
    asm volatile("ldmatrix.sync.aligned.m8n8.x4.shared.b16 {%0,%1,%2,%3}, [%4];"
                 : "=r"(r[0]), "=r"(r[1]), "=r"(r[2]), "=r"(r[3]) : "r"(addr));
}
__device__ __forceinline__ void mma16816(float* c, const uint32_t* a, uint32_t b0, uint32_t b1) {
    asm volatile("mma.sync.aligned.m16n8k16.row.col.f32.f16.f16.f32 "
                 "{%0,%1,%2,%3}, {%4,%5,%6,%7}, {%8,%9}, {%0,%1,%2,%3};"
                 : "+f"(c[0]), "+f"(c[1]), "+f"(c[2]), "+f"(c[3])
                 : "r"(a[0]), "r"(a[1]), "r"(a[2]), "r"(a[3]), "r"(b0), "r"(b1));
}

template<int OUTMODE>   // 0 = fp32, 1 = split hi/lo, 2 = hi only
__global__ __launch_bounds__(256, 2)
void gemm_hmma_x2(const __half* __restrict__ Ah,
                  const __half* __restrict__ Bh, const __half* __restrict__ Bl,
                  float* __restrict__ Cf,
                  __half* __restrict__ Ch, __half* __restrict__ Cl,
                  int M, int N, int K)
{
    extern __shared__ __align__(128) char smem[];
    const uint32_t sb = (uint32_t)__cvta_generic_to_shared(smem);

    const int tid = threadIdx.x;
    const int lane = tid & 31;
    const int wid = tid >> 5;
    const int wm = (wid >> 2) * 64;
    const int wn = (wid & 3) * 32;
    const int g = lane >> 3, r8 = lane & 7;

    const int e = blockIdx.z;
    const size_t MK = (size_t)M * K, NK = (size_t)N * K, MN = (size_t)M * N;
    const __half *Ahe = Ah + e * MK;
    const __half *Bhe = Bh + e * NK, *Ble = Bl + e * NK;
    const int bm = blockIdx.y * BM, bn = blockIdx.x * BN;

    float acc[4][4][4];
    #pragma unroll
    for (int i = 0; i < 4; i++)
        #pragma unroll
        for (int j = 0; j < 4; j++)
            #pragma unroll
            for (int q = 0; q < 4; q++) acc[i][j][q] = 0.0f;

    const int NC = K / BKC;

    const int cr0 = tid >> 2,          cc0 = tid & 3;
    const int cr1 = (tid + 256) >> 2,  cc1 = (tid + 256) & 3;

    auto load_chunk = [&](int c, int buf) {
        const int k0 = c * BKC;
        const uint32_t b = sb + (uint32_t)buf * BUFB;
        cp16(b + cr0 * ROWB + cc0 * 16, Ahe + (size_t)(bm + cr0) * K + k0 + cc0 * 8);
        cp16(b + cr1 * ROWB + cc1 * 16, Ahe + (size_t)(bm + cr1) * K + k0 + cc1 * 8);
        cp16(b + TILEB + cr0 * ROWB + cc0 * 16, Bhe + (size_t)(bn + cr0) * K + k0 + cc0 * 8);
        cp16(b + TILEB + cr1 * ROWB + cc1 * 16, Bhe + (size_t)(bn + cr1) * K + k0 + cc1 * 8);
        cp16(b + 2 * TILEB + cr0 * ROWB + cc0 * 16, Ble + (size_t)(bn + cr0) * K + k0 + cc0 * 8);
        cp16(b + 2 * TILEB + cr1 * ROWB + cc1 * 16, Ble + (size_t)(bn + cr1) * K + k0 + cc1 * 8);
        asm volatile("cp.async.commit_group;" ::: "memory");
    };

    load_chunk(0, 0);
    load_chunk(1, 1);

    for (int c = 0; c < NC; c++) {
        // chunk c complete iff at most the newest group (chunk c+1) is outstanding
        asm volatile("cp.async.wait_group 1;" ::: "memory");
        __syncthreads();   // also guards: everyone finished compute(c-1) before
                           // buffer (c+2)%3 (which held chunk c-1) is overwritten
        if (c + 2 < NC) load_chunk(c + 2, (c + 2) % 3);
        else asm volatile("cp.async.commit_group;" ::: "memory");  // keep counts uniform

        const uint32_t As = sb + (uint32_t)(c % 3) * BUFB;
        const uint32_t Bs  = As + TILEB;
        const uint32_t Bls = As + 2 * TILEB;

        #pragma unroll
        for (int ks = 0; ks < 2; ks++) {
            uint32_t ah[4][4], bbh[2][4], bbl[2][4];
            #pragma unroll
            for (int ti = 0; ti < 4; ti++) {
                uint32_t off = (uint32_t)(wm + ti * 16 + (g & 1) * 8 + r8) * ROWB
                             + ks * 32 + (g >> 1) * 16;
                ldm4(ah[ti], As + off);
            }
            #pragma unroll
            for (int p = 0; p < 2; p++) {
                uint32_t off = (uint32_t)(wn + p * 16 + (g >> 1) * 8 + r8) * ROWB
                             + ks * 32 + (g & 1) * 16;
                ldm4(bbh[p], Bs + off);
                ldm4(bbl[p], Bls + off);
            }
            #pragma unroll
            for (int ti = 0; ti < 4; ti++)
                #pragma unroll
                for (int tj = 0; tj < 4; tj++) {
                    mma16816(acc[ti][tj], ah[ti],
                             bbh[tj >> 1][(tj & 1) * 2], bbh[tj >> 1][(tj & 1) * 2 + 1]);
                    mma16816(acc[ti][tj], ah[ti],
                             bbl[tj >> 1][(tj & 1) * 2], bbl[tj >> 1][(tj & 1) * 2 + 1]);
                }
        }
    }

    // epilogue
    #pragma unroll
    for (int ti = 0; ti < 4; ti++)
        #pragma unroll
        for (int tj = 0; tj < 4; tj++) {
            const int row = bm + wm + ti * 16 + (lane >> 2);
            const int col = bn + wn + tj * 8 + (lane & 3) * 2;
            if (OUTMODE == 1) {
                __half h0, l0, h1, l1;
                split1(acc[ti][tj][0], h0, l0); split1(acc[ti][tj][1], h1, l1);
                __half hp[2] = {h0, h1}, lp[2] = {l0, l1};
                *(uint32_t*)(Ch + e * MN + (size_t)row * N + col) = *(uint32_t*)hp;
                *(uint32_t*)(Cl + e * MN + (size_t)row * N + col) = *(uint32_t*)lp;
                split1(acc[ti][tj][2], h0, l0); split1(acc[ti][tj][3], h1, l1);
                __half hq[2] = {h0, h1}, lq[2] = {l0, l1};
                *(uint32_t*)(Ch + e * MN + (size_t)(row + 8) * N + col) = *(uint32_t*)hq;
                *(uint32_t*)(Cl + e * MN + (size_t)(row + 8) * N + col) = *(uint32_t*)lq;
            } else if (OUTMODE == 2) {
                __half hp[2] = {__float2half(acc[ti][tj][0]), __float2half(acc[ti][tj][1])};
                __half hq[2] = {__float2half(acc[ti][tj][2]), __float2half(acc[ti][tj][3])};
                *(uint32_t*)(Ch + e * MN + (size_t)row * N + col) = *(uint32_t*)hp;
                *(uint32_t*)(Ch + e * MN + (size_t)(row + 8) * N + col) = *(uint32_t*)hq;
            } else {
                float* cp0 = Cf + e * MN + (size_t)row * N + col;
                float* cp1 = Cf + e * MN + (size_t)(row + 8) * N + col;
                *(float2*)cp0 = make_float2(acc[ti][tj][0], acc[ti][tj][1]);
                *(float2*)cp1 = make_float2(acc[ti][tj][2], acc[ti][tj][3]);
            }
        }
}

// ---------------- launcher ----------------
extern "C" void kernel_launch(void* const* d_in, const int* in_sizes, int n_in,
                              void* d_out, int out_size)
{
    (void)in_sizes; (void)n_in; (void)out_size;
    const float* x  = (const float*)d_in[0];
    const float* w1 = (const float*)d_in[1];
    const float* w2 = (const float*)d_in[2];
    const float* w3 = (const float*)d_in[3];
    const float* w4 = (const float*)d_in[4];
    float* out = (float*)d_out;

    __half *xh,*w1h,*w2h,*w2l,*w3h,*w3l,*w4h;
    __half *W12h,*W12l,*W34h,*Wth,*Wtl;
    cudaGetSymbolAddress((void**)&xh,  g_xh);
    cudaGetSymbolAddress((void**)&w1h, g_w1h);
    cudaGetSymbolAddress((void**)&w2h, g_w2h); cudaGetSymbolAddress((void**)&w2l, g_w2l);
    cudaGetSymbolAddress((void**)&w3h, g_w3h); cudaGetSymbolAddress((void**)&w3l, g_w3l);
    cudaGetSymbolAddress((void**)&w4h, g_w4h);
    cudaGetSymbolAddress((void**)&W12h, g_W12h); cudaGetSymbolAddress((void**)&W12l, g_W12l);
    cudaGetSymbolAddress((void**)&W34h, g_W34h);
    cudaGetSymbolAddress((void**)&Wth,  g_Wth);  cudaGetSymbolAddress((void**)&Wtl,  g_Wtl);

    cudaFuncSetAttribute(gemm_hmma_x2<0>, cudaFuncAttributeMaxDynamicSharedMemorySize, SMEMB);
    cudaFuncSetAttribute(gemm_hmma_x2<1>, cudaFuncAttributeMaxDynamicSharedMemorySize, SMEMB);
    cudaFuncSetAttribute(gemm_hmma_x2<2>, cudaFuncAttributeMaxDynamicSharedMemorySize, SMEMB);

    // conversions
    {
        int n4 = NE * NT * NH / 4;
        half_rm<<<n4 / 256, 256>>>((const float4*)x, (uint2*)xh, n4);
    }
    {
        int n4 = NE * NH * NI / 4;
        half_rm<<<n4 / 256, 256>>>((const float4*)w1, (uint2*)w1h, n4);
        split_rm<<<n4 / 256, 256>>>((const float4*)w3, (uint2*)w3h, (uint2*)w3l, n4);
    }
    split_tr<<<dim3(NH / 32, NI / 32, NE), 256>>>(w2, w2h, w2l, NI, NH);
    half_tr <<<dim3(NH / 32, NI / 32, NE), 256>>>(w4, w4h, NI, NH);

    // S1: W12 = w1 @ w2        (A=w1 hi,  B=w2^T hi/lo)   M=N=1024, K=512 -> split out
    gemm_hmma_x2<1><<<dim3(NH / BN, NH / BM, NE), 256, SMEMB>>>(
        w1h, w2h, w2l, nullptr, W12h, W12l, NH, NH, NI);
    // S2: W34^T = w4^T @ w3^T  (A=w4^T hi, B=w3 hi/lo)    M=N=1024, K=512 -> hi out
    gemm_hmma_x2<2><<<dim3(NH / BN, NH / BM, NE), 256, SMEMB>>>(
        w4h, w3h, w3l, nullptr, W34h, nullptr, NH, NH, NI);
    // S3: W^T = W34^T @ W12^T  (A=W34t hi, B=W12 hi/lo)   M=N=K=1024 -> split out
    gemm_hmma_x2<1><<<dim3(NH / BN, NH / BM, NE), 256, SMEMB>>>(
        W34h, W12h, W12l, nullptr, Wth, Wtl, NH, NH, NH);
    // S4: out = x @ W          (A=x hi,   B=W^T hi/lo)    M=4096, N=K=1024 -> fp32
    gemm_hmma_x2<0><<<dim3(NH / BN, NT / BM, NE), 256, SMEMB>>>(
        xh, Wth, Wtl, out, nullptr, nullptr, NT, NH, NH);
}

// round 11
// speedup vs baseline: 1.8664x; 1.3060x over previous
#include <cuda_runtime.h>
#include <cuda_fp16.h>
#include <cstdint>

// out = x @ (w1@w2@w3@w4) per expert, rank-512 factored:
//   V = w2@w3@w4 (prep, small), then h = x@w1, out = h@V.
// Every GEMM = fp16 2-term: D = Ah @ (Bh + Bl)^T, A hi-only, B split hi/lo.
// HMMA-equivalent work: 155 GFLOP (was 206). mma.sync.m16n8k16 f16 (sm_80+ PTX).
// R9: rank factorization (-25% MMA count); h written as fp16 directly in epilogue.

#define NE 8
#define NT 4096
#define NH 1024
#define NI 512

// ---------------- scratch ----------------
__device__ __align__(128) __half g_xh[NE*NT*NH];                      // x hi
__device__ __align__(128) __half g_w1th[NE*NI*NH], g_w1tl[NE*NI*NH];  // w1^T hi/lo [E,512,1024]
__device__ __align__(128) __half g_w2h[NE*NI*NH];                     // w2 hi (as-is) [E,512,1024]
__device__ __align__(128) __half g_w3th[NE*NI*NH], g_w3tl[NE*NI*NH];  // w3^T hi/lo [E,512,1024]
__device__ __align__(128) __half g_w4th[NE*NH*NI];                    // w4^T hi [E,1024,512]
__device__ __align__(128) __half g_Ph[NE*NI*NI],   g_Pl[NE*NI*NI];    // P = w2@w3 [E,512,512]
__device__ __align__(128) __half g_Vth[NE*NH*NI],  g_Vtl[NE*NH*NI];   // V^T hi/lo [E,1024,512]
__device__ __align__(128) __half g_h[NE*NT*NI];                       // h = x@w1 hi [E,4096,512]

__device__ __forceinline__ void split1(float v, __half& h, __half& l) {
    h = __float2half(v);
    l = __float2half(v - __half2float(h));
}

// ---------------- conversion kernels ----------------
__global__ __launch_bounds__(256)
void half_rm(const float4* __restrict__ in, uint2* __restrict__ hi, int n4) {
    int i = blockIdx.x * 256 + threadIdx.x;
    if (i >= n4) return;
    float4 v = in[i];
    __half h[4] = {__float2half(v.x), __float2half(v.y),
                   __float2half(v.z), __float2half(v.w)};
    hi[i] = *(uint2*)h;
}

// in: [E, R, C] fp32 -> out hi: [E, C, R]
__global__ __launch_bounds__(256)
void half_tr(const float* __restrict__ in, __half* __restrict__ hi, int R, int C) {
    __shared__ float t[32][33];
    const int e = blockIdx.z;
    const float* ine = in + (size_t)e * R * C;
    __half* he = hi + (size_t)e * R * C;
    const int r0 = blockIdx.y * 32, c0 = blockIdx.x * 32;
    const int tx = threadIdx.x & 31, ty = threadIdx.x >> 5;
    #pragma unroll
    for (int i = 0; i < 32; i += 8)
        t[ty + i][tx] = ine[(size_t)(r0 + ty + i) * C + c0 + tx];
    __syncthreads();
    #pragma unroll
    for (int i = 0; i < 32; i += 8)
        he[(size_t)(c0 + ty + i) * R + r0 + tx] = __float2half(t[tx][ty + i]);
}

// in: [E, R, C] fp32 -> out hi/lo: [E, C, R]
__global__ __launch_bounds__(256)
void split_tr(const float* __restrict__ in, __half* __restrict__ hi,
              __half* __restrict__ lo, int R, int C) {
    __shared__ float t[32][33];
    const int e = blockIdx.z;
    const float* ine = in + (size_t)e * R * C;
    __half* he = hi + (size_t)e * R * C;
    __half* le = lo + (size_t)e * R * C;
    const int r0 = blockIdx.y * 32, c0 = blockIdx.x * 32;
    const int tx = threadIdx.x & 31, ty = threadIdx.x >> 5;
    #pragma unroll
    for (int i = 0; i < 32; i += 8)
        t[ty + i][tx] = ine[(size_t)(r0 + ty + i) * C + c0 + tx];
    __syncthreads();
    #pragma unroll
    for (int i = 0; i < 32; i += 8) {
        __half h, l;
        split1(t[tx][ty + i], h, l);
        he[(size_t)(c0 + ty + i) * R + r0 + tx] = h;
        le[(size_t)(c0 + ty + i) * R + r0 + tx] = l;
    }
}

// ---------------- HMMA fp16 2-term GEMM ----------------
// CTA 128x128, BK=32. 8 warps 2(M) x 4(N); warp tile 64x32.
// SMEM rows padded to 80B. 3-stage cp.async ring, 1 sync per chunk.
#define BM 128
#define BN 128
#define BKC 32
#define ROWB 80u
#define TILEB (128u * ROWB)       // 10240 B per 128x32 tile
#define BUFB (3u * TILEB)         // Ah | Bh | Bl = 30720 B
#define SMEMB (3u * BUFB)         // 92160 B

__device__ __forceinline__ void cp16(uint32_t s, const void* g) {
    asm volatile("cp.async.cg.shared.global [%0], [%1], 16;" :: "r"(s), "l"(g));
}
__device__ __forceinline__ void ldm4(uint32_t* r, uint32_t addr) {
    asm volatile("ldmatrix.sync.aligned.m8n8.x4.shared.b16 {%0,%1,%2,%3}, [%4];"
                 : "=r"(r[0]), "=r"(r[1]), "=r"(r[2]), "=r"(r[3]) : "r"(addr));
}
__device__ __forceinline__ void mma16816(float* c, const uint32_t* a, uint32_t b0, uint32_t b1) {
    asm volatile("mma.sync.aligned.m16n8k16.row.col.f32.f16.f16.f32 "
                 "{%0,%1,%2,%3}, {%4,%5,%6,%7}, {%8,%9}, {%0,%1,%2,%3};"
                 : "+f"(c[0]), "+f"(c[1]), "+f"(c[2]), "+f"(c[3])
                 : "r"(a[0]), "r"(a[1]), "r"(a[2]), "r"(a[3]), "r"(b0), "r"(b1));
}

template<int OUTMODE>   // 0 = fp32, 1 = split hi/lo, 2 = hi only
__global__ __launch_bounds__(256, 2)
void gemm_hmma_x2(const __half* __restrict__ Ah,
                  const __half* __restrict__ Bh, const __half* __restrict__ Bl,
                  float* __restrict__ Cf,
                  __half* __restrict__ Ch, __half* __restrict__ Cl,
                  int M, int N, int K)
{
    extern __shared__ __align__(128) char smem[];
    const uint32_t sb = (uint32_t)__cvta_generic_to_shared(smem);

    const int tid = threadIdx.x;
    const int lane = tid & 31;
    const int wid = tid >> 5;
    const int wm = (wid >> 2) * 64;
    const int wn = (wid & 3) * 32;
    const int g = lane >> 3, r8 = lane & 7;

    const int e = blockIdx.z;
    const size_t MK = (size_t)M * K, NK = (size_t)N * K, MN = (size_t)M * N;
    const __half *Ahe = Ah + e * MK;
    const __half *Bhe = Bh + e * NK, *Ble = Bl + e * NK;
    const int bm = blockIdx.y * BM, bn = blockIdx.x * BN;

    float acc[4][4][4];
    #pragma unroll
    for (int i = 0; i < 4; i++)
        #pragma unroll
        for (int j = 0; j < 4; j++)
            #pragma unroll
            for (int q = 0; q < 4; q++) acc[i][j][q] = 0.0f;

    const int NC = K / BKC;

    const int cr0 = tid >> 2,          cc0 = tid & 3;
    const int cr1 = (tid + 256) >> 2,  cc1 = (tid + 256) & 3;

    auto load_chunk = [&](int c, int buf) {
        const int k0 = c * BKC;
        const uint32_t b = sb + (uint32_t)buf * BUFB;
        cp16(b + cr0 * ROWB + cc0 * 16, Ahe + (size_t)(bm + cr0) * K + k0 + cc0 * 8);
        cp16(b + cr1 * ROWB + cc1 * 16, Ahe + (size_t)(bm + cr1) * K + k0 + cc1 * 8);
        cp16(b + TILEB + cr0 * ROWB + cc0 * 16, Bhe + (size_t)(bn + cr0) * K + k0 + cc0 * 8);
        cp16(b + TILEB + cr1 * ROWB + cc1 * 16, Bhe + (size_t)(bn + cr1) * K + k0 + cc1 * 8);
        cp16(b + 2 * TILEB + cr0 * ROWB + cc0 * 16, Ble + (size_t)(bn + cr0) * K + k0 + cc0 * 8);
        cp16(b + 2 * TILEB + cr1 * ROWB + cc1 * 16, Ble + (size_t)(bn + cr1) * K + k0 + cc1 * 8);
        asm volatile("cp.async.commit_group;" ::: "memory");
    };

    load_chunk(0, 0);
    load_chunk(1, 1);

    for (int c = 0; c < NC; c++) {
        asm volatile("cp.async.wait_group 1;" ::: "memory");
        __syncthreads();
        if (c + 2 < NC) load_chunk(c + 2, (c + 2) % 3);
        else asm volatile("cp.async.commit_group;" ::: "memory");

        const uint32_t As = sb + (uint32_t)(c % 3) * BUFB;
        const uint32_t Bs  = As + TILEB;
        const uint32_t Bls = As + 2 * TILEB;

        #pragma unroll
        for (int ks = 0; ks < 2; ks++) {
            uint32_t ah[4][4], bbh[2][4], bbl[2][4];
            #pragma unroll
            for (int ti = 0; ti < 4; ti++) {
                uint32_t off = (uint32_t)(wm + ti * 16 + (g & 1) * 8 + r8) * ROWB
                             + ks * 32 + (g >> 1) * 16;
                ldm4(ah[ti], As + off);
            }
            #pragma unroll
            for (int p = 0; p < 2; p++) {
                uint32_t off = (uint32_t)(wn + p * 16 + (g >> 1) * 8 + r8) * ROWB
                             + ks * 32 + (g & 1) * 16;
                ldm4(bbh[p], Bs + off);
                ldm4(bbl[p], Bls + off);
            }
            #pragma unroll
            for (int ti = 0; ti < 4; ti++)
                #pragma unroll
                for (int tj = 0; tj < 4; tj++) {
                    mma16816(acc[ti][tj], ah[ti],
                             bbh[tj >> 1][(tj & 1) * 2], bbh[tj >> 1][(tj & 1) * 2 + 1]);
                    mma16816(acc[ti][tj], ah[ti],
                             bbl[tj >> 1][(tj & 1) * 2], bbl[tj >> 1][(tj & 1) * 2 + 1]);
                }
        }
    }

    // epilogue
    #pragma unroll
    for (int ti = 0; ti < 4; ti++)
        #pragma unroll
        for (int tj = 0; tj < 4; tj++) {
            const int row = bm + wm + ti * 16 + (lane >> 2);
            const int col = bn + wn + tj * 8 + (lane & 3) * 2;
            if (OUTMODE == 1) {
                __half h0, l0, h1, l1;
                split1(acc[ti][tj][0], h0, l0); split1(acc[ti][tj][1], h1, l1);
                __half hp[2] = {h0, h1}, lp[2] = {l0, l1};
                *(uint32_t*)(Ch + e * MN + (size_t)row * N + col) = *(uint32_t*)hp;
                *(uint32_t*)(Cl + e * MN + (size_t)row * N + col) = *(uint32_t*)lp;
                split1(acc[ti][tj][2], h0, l0); split1(acc[ti][tj][3], h1, l1);
                __half hq[2] = {h0, h1}, lq[2] = {l0, l1};
                *(uint32_t*)(Ch + e * MN + (size_t)(row + 8) * N + col) = *(uint32_t*)hq;
                *(uint32_t*)(Cl + e * MN + (size_t)(row + 8) * N + col) = *(uint32_t*)lq;
            } else if (OUTMODE == 2) {
                __half hp[2] = {__float2half(acc[ti][tj][0]), __float2half(acc[ti][tj][1])};
                __half hq[2] = {__float2half(acc[ti][tj][2]), __float2half(acc[ti][tj][3])};
                *(uint32_t*)(Ch + e * MN + (size_t)row * N + col) = *(uint32_t*)hp;
                *(uint32_t*)(Ch + e * MN + (size_t)(row + 8) * N + col) = *(uint32_t*)hq;
            } else {
                float* cp0 = Cf + e * MN + (size_t)row * N + col;
                float* cp1 = Cf + e * MN + (size_t)(row + 8) * N + col;
                *(float2*)cp0 = make_float2(acc[ti][tj][0], acc[ti][tj][1]);
                *(float2*)cp1 = make_float2(acc[ti][tj][2], acc[ti][tj][3]);
            }
        }
}

// ---------------- launcher ----------------
extern "C" void kernel_launch(void* const* d_in, const int* in_sizes, int n_in,
                              void* d_out, int out_size)
{
    (void)in_sizes; (void)n_in; (void)out_size;
    const float* x  = (const float*)d_in[0];
    const float* w1 = (const float*)d_in[1];
    const float* w2 = (const float*)d_in[2];
    const float* w3 = (const float*)d_in[3];
    const float* w4 = (const float*)d_in[4];
    float* out = (float*)d_out;

    __half *xh,*w1th,*w1tl,*w2h,*w3th,*w3tl,*w4th,*Ph,*Pl,*Vth,*Vtl,*hbuf;
    cudaGetSymbolAddress((void**)&xh,   g_xh);
    cudaGetSymbolAddress((void**)&w1th, g_w1th); cudaGetSymbolAddress((void**)&w1tl, g_w1tl);
    cudaGetSymbolAddress((void**)&w2h,  g_w2h);
    cudaGetSymbolAddress((void**)&w3th, g_w3th); cudaGetSymbolAddress((void**)&w3tl, g_w3tl);
    cudaGetSymbolAddress((void**)&w4th, g_w4th);
    cudaGetSymbolAddress((void**)&Ph,   g_Ph);   cudaGetSymbolAddress((void**)&Pl,   g_Pl);
    cudaGetSymbolAddress((void**)&Vth,  g_Vth);  cudaGetSymbolAddress((void**)&Vtl,  g_Vtl);
    cudaGetSymbolAddress((void**)&hbuf, g_h);

    cudaFuncSetAttribute(gemm_hmma_x2<0>, cudaFuncAttributeMaxDynamicSharedMemorySize, SMEMB);
    cudaFuncSetAttribute(gemm_hmma_x2<1>, cudaFuncAttributeMaxDynamicSharedMemorySize, SMEMB);
    cudaFuncSetAttribute(gemm_hmma_x2<2>, cudaFuncAttributeMaxDynamicSharedMemorySize, SMEMB);

    // idx 0: w2 hi (as-is, A operand of P)
    {
        int n4 = NE * NI * NH / 4;
        half_rm<<<n4 / 256, 256>>>((const float4*)w2, (uint2*)w2h, n4);
    }
    // idx 1: w3 -> w3^T hi/lo  ([E,1024,512] -> [E,512,1024])
    split_tr<<<dim3(NI / 32, NH / 32, NE), 256>>>(w3, w3th, w3tl, NH, NI);
    // idx 2: P = w2 @ w3  (A=w2 hi, Bt=w3^T hi/lo)  M=512,N=512,K=1024 -> split out
    gemm_hmma_x2<1><<<dim3(NI / BN, NI / BM, NE), 256, SMEMB>>>(
        w2h, w3th, w3tl, nullptr, Ph, Pl, NI, NI, NH);
    // idx 3: w1 -> w1^T hi/lo  ([E,1024,512] -> [E,512,1024])
    split_tr<<<dim3(NI / 32, NH / 32, NE), 256>>>(w1, w1th, w1tl, NH, NI);
    // idx 4: x hi
    {
        int n4 = NE * NT * NH / 4;
        half_rm<<<n4 / 256, 256>>>((const float4*)x, (uint2*)xh, n4);
    }
    // idx 5 (ncu capture): h = x @ w1  (A=x hi, Bt=w1^T hi/lo)  M=4096,N=512,K=1024 -> hi out
    gemm_hmma_x2<2><<<dim3(NI / BN, NT / BM, NE), 256, SMEMB>>>(
        xh, w1th, w1tl, nullptr, hbuf, nullptr, NT, NI, NH);
    // idx 6: w4 -> w4^T hi  ([E,512,1024] -> [E,1024,512])
    half_tr<<<dim3(NH / 32, NI / 32, NE), 256>>>(w4, w4th, NI, NH);
    // idx 7: V^T = w4^T @ P^T  (A=w4^T hi, Bt=P hi/lo)  M=1024,N=512,K=512 -> split out
    gemm_hmma_x2<1><<<dim3(NI / BN, NH / BM, NE), 256, SMEMB>>>(
        w4th, Ph, Pl, nullptr, Vth, Vtl, NH, NI, NI);
    // idx 8: out = h @ V  (A=h hi, Bt=V^T hi/lo)  M=4096,N=1024,K=512 -> fp32
    gemm_hmma_x2<0><<<dim3(NH / BN, NT / BM, NE), 256, SMEMB>>>(
        hbuf, Vth, Vtl, out, nullptr, nullptr, NT, NH, NI);
}